// round 6
// baseline (speedup 1.0000x reference)
#include <cuda_runtime.h>
#include <cuda_bf16.h>
#include <math.h>

// ---------------- problem constants ----------------
#define DIMC    96
#define NHC     3
#define HEADC   32
#define WSC     7
#define SHIFTC  3
#define PC      5
#define HC      56
#define NWC     64
#define TPC     320
#define NNC     54
#define BATCHC  64
#define TOKC    3456
#define MROWS   (BATCHC * NWC * NNC)   // 221184
#define HIDC    384
#define SCALEC  0.17677669529663687f

// ---------------- scratch (split format: uint2{hi bf16 pair, lo bf16 pair}) ----------------
__device__ __align__(16) uint2 g_xw_sp   [MROWS * 48];            // LN1 out, window order
__device__ float               g_qkv     [(size_t)MROWS * 3 * DIMC];
__device__ __align__(16) uint2 g_attno_sp[MROWS * 48];            // attn out, window order
__device__ float               g_y       [MROWS * DIMC];          // residual stream (fp32)
__device__ __align__(16) uint2 g_yn_sp   [MROWS * 48];            // LN2 out
__device__ __align__(16) uint2 g_h_sp    [(size_t)MROWS * 192];   // fc1+GELU out
// pre-split weights [kpair][n]
__device__ __align__(16) uint2 g_wq_sp[48 * 288];
__device__ __align__(16) uint2 g_wp_sp[48 * 96];
__device__ __align__(16) uint2 g_w1_sp[48 * 384];
__device__ __align__(16) uint2 g_w2_sp[192 * 96];

__device__ __forceinline__ int map_token(int bw, int n) {
    int b = bw >> 6;
    int w = bw & 63;
    int tok;
    if (n < PC) {
        tok = w * PC + n;
    } else {
        int p  = n - PC;
        int r  = p / 7, c = p % 7;
        int wh = w >> 3, ww = w & 7;
        int hr = wh * 7 + r + SHIFTC; if (hr >= HC) hr -= HC;
        int wc = ww * 7 + c + SHIFTC; if (wc >= HC) wc -= HC;
        tok = TPC + hr * HC + wc;
    }
    return b * TOKC + tok;
}

__device__ __forceinline__ float warp_sum(float v) {
    #pragma unroll
    for (int o = 16; o; o >>= 1) v += __shfl_xor_sync(0xffffffffu, v, o);
    return v;
}

__device__ __forceinline__ uint2 split_bf16_pair(float x0, float x1) {
    __nv_bfloat16 h0 = __float2bfloat16(x0);
    __nv_bfloat16 h1 = __float2bfloat16(x1);
    float r0 = x0 - __bfloat162float(h0);
    float r1 = x1 - __bfloat162float(h1);
    __nv_bfloat16 l0 = __float2bfloat16(r0);
    __nv_bfloat16 l1 = __float2bfloat16(r1);
    uint2 o;
    o.x = ((unsigned)__bfloat16_as_ushort(h1) << 16) | (unsigned)__bfloat16_as_ushort(h0);
    o.y = ((unsigned)__bfloat16_as_ushort(l1) << 16) | (unsigned)__bfloat16_as_ushort(l0);
    return o;
}

// ---------------- weight pre-split ----------------
__global__ __launch_bounds__(256)
void split_w_kernel(const float* __restrict__ qkv_w, const float* __restrict__ proj_w,
                    const float* __restrict__ fc1_w, const float* __restrict__ fc2_w) {
    int i = blockIdx.x * blockDim.x + threadIdx.x;
    if (i < 13824) {
        int kp = i / 288, n = i % 288;
        g_wq_sp[i] = split_bf16_pair(qkv_w[(2 * kp) * 288 + n], qkv_w[(2 * kp + 1) * 288 + n]);
    } else if (i < 18432) {
        int j = i - 13824, kp = j / 96, n = j % 96;
        g_wp_sp[j] = split_bf16_pair(proj_w[(2 * kp) * 96 + n], proj_w[(2 * kp + 1) * 96 + n]);
    } else if (i < 36864) {
        int j = i - 18432, kp = j / 384, n = j % 384;
        g_w1_sp[j] = split_bf16_pair(fc1_w[(2 * kp) * 384 + n], fc1_w[(2 * kp + 1) * 384 + n]);
    } else if (i < 55296) {
        int j = i - 36864, kp = j / 96, n = j % 96;
        g_w2_sp[j] = split_bf16_pair(fc2_w[(2 * kp) * 96 + n], fc2_w[(2 * kp + 1) * 96 + n]);
    }
}

// ---------------- LN kernels (write split pairs) ----------------
__global__ __launch_bounds__(256)
void ln_gather_kernel(const float* __restrict__ x,
                      const float* __restrict__ g, const float* __restrict__ bta) {
    int row  = (blockIdx.x * blockDim.x + threadIdx.x) >> 5;
    int lane = threadIdx.x & 31;
    if (row >= MROWS) return;
    int bw = row / NNC, n = row % NNC;
    const float2* src2 = (const float2*)(x + (size_t)map_token(bw, n) * DIMC);
    float2 a0 = src2[lane];
    float2 a1 = make_float2(0.f, 0.f);
    if (lane < 16) a1 = src2[32 + lane];
    float s = a0.x + a0.y + a1.x + a1.y;
    float mean = warp_sum(s) * (1.f / 96.f);
    float d0x = a0.x - mean, d0y = a0.y - mean;
    float d1x = a1.x - mean, d1y = a1.y - mean;
    float vq = d0x * d0x + d0y * d0y + (lane < 16 ? d1x * d1x + d1y * d1y : 0.f);
    float var = warp_sum(vq) * (1.f / 96.f);
    float inv = rsqrtf(var + 1e-5f);
    const float2* g2 = (const float2*)g;
    const float2* b2 = (const float2*)bta;
    uint2* dst = g_xw_sp + (size_t)row * 48;
    float2 G = g2[lane], B = b2[lane];
    dst[lane] = split_bf16_pair(d0x * inv * G.x + B.x, d0y * inv * G.y + B.y);
    if (lane < 16) {
        float2 G1 = g2[32 + lane], B1 = b2[32 + lane];
        dst[32 + lane] = split_bf16_pair(d1x * inv * G1.x + B1.x, d1y * inv * G1.y + B1.y);
    }
}

__global__ __launch_bounds__(256)
void ln_plain_kernel(const float* __restrict__ y,
                     const float* __restrict__ g, const float* __restrict__ bta) {
    int row  = (blockIdx.x * blockDim.x + threadIdx.x) >> 5;
    int lane = threadIdx.x & 31;
    if (row >= MROWS) return;
    const float2* src2 = (const float2*)(y + (size_t)row * DIMC);
    float2 a0 = src2[lane];
    float2 a1 = make_float2(0.f, 0.f);
    if (lane < 16) a1 = src2[32 + lane];
    float s = a0.x + a0.y + a1.x + a1.y;
    float mean = warp_sum(s) * (1.f / 96.f);
    float d0x = a0.x - mean, d0y = a0.y - mean;
    float d1x = a1.x - mean, d1y = a1.y - mean;
    float vq = d0x * d0x + d0y * d0y + (lane < 16 ? d1x * d1x + d1y * d1y : 0.f);
    float var = warp_sum(vq) * (1.f / 96.f);
    float inv = rsqrtf(var + 1e-5f);
    const float2* g2 = (const float2*)g;
    const float2* b2 = (const float2*)bta;
    uint2* dst = g_yn_sp + (size_t)row * 48;
    float2 G = g2[lane], B = b2[lane];
    dst[lane] = split_bf16_pair(d0x * inv * G.x + B.x, d0y * inv * G.y + B.y);
    if (lane < 16) {
        float2 G1 = g2[32 + lane], B1 = b2[32 + lane];
        dst[32 + lane] = split_bf16_pair(d1x * inv * G1.x + B1.x, d1y * inv * G1.y + B1.y);
    }
}

// ---------------- BF16x3 tensor-core GEMM (unchanged) ----------------
__device__ __forceinline__ void mma16(float c[4],
                                      unsigned a0, unsigned a1, unsigned a2, unsigned a3,
                                      unsigned b0, unsigned b1) {
    asm volatile("mma.sync.aligned.m16n8k16.row.col.f32.bf16.bf16.f32 "
                 "{%0,%1,%2,%3}, {%4,%5,%6,%7}, {%8,%9}, {%0,%1,%2,%3};\n"
                 : "+f"(c[0]), "+f"(c[1]), "+f"(c[2]), "+f"(c[3])
                 : "r"(a0), "r"(a1), "r"(a2), "r"(a3), "r"(b0), "r"(b1));
}

#define GEMM_SMEM ((2 * 16 * 132 + 2 * 16 * 100) * 8)   // 59392 bytes

template<int MODE>
__global__ __launch_bounds__(256, 2)
void gemm_tc(const uint2* __restrict__ A, const uint2* __restrict__ Bw,
             const float* __restrict__ bias, const float* __restrict__ res,
             float* __restrict__ out, uint2* __restrict__ outp, int N, int K) {
    extern __shared__ uint2 smemu[];
    uint2 (*As2)[16][132] = reinterpret_cast<uint2(*)[16][132]>(smemu);
    uint2 (*Bs2)[16][100] = reinterpret_cast<uint2(*)[16][100]>(smemu + 2 * 16 * 132);

    const int tid  = threadIdx.x;
    const int wid  = tid >> 5, lane = tid & 31;
    const int gid  = lane >> 2, tig = lane & 3;
    const int wm   = (wid >> 1) * 32;
    const int wn   = (wid & 1) * 48;
    const int m0   = blockIdx.y * 128;
    const int n0   = blockIdx.x * 96;
    const int KP   = K >> 1;

    int arow[4], akp[4];
    const uint2* aPtr[4];
    #pragma unroll
    for (int j = 0; j < 4; j++) {
        int c = tid + 256 * j;
        arow[j] = c >> 3;
        akp[j]  = (c & 7) * 2;
        aPtr[j] = A + (size_t)(m0 + arow[j]) * KP + akp[j];
    }
    int bkp[3], bn2[3];
    const uint2* bPtr[3];
    #pragma unroll
    for (int j = 0; j < 3; j++) {
        int c = tid + 256 * j;
        bkp[j] = c / 48;
        bn2[j] = (c % 48) * 2;
        bPtr[j] = Bw + (size_t)bkp[j] * N + n0 + bn2[j];
    }

    float acc[2][6][4];
    #pragma unroll
    for (int i = 0; i < 2; i++)
        #pragma unroll
        for (int j = 0; j < 6; j++)
            #pragma unroll
            for (int r = 0; r < 4; r++) acc[i][j][r] = 0.f;

    uint4 aR[4], bR[3];
    #pragma unroll
    for (int j = 0; j < 4; j++) aR[j] = *(const uint4*)(aPtr[j]);
    #pragma unroll
    for (int j = 0; j < 3; j++) bR[j] = *(const uint4*)(bPtr[j]);

    #pragma unroll
    for (int j = 0; j < 4; j++) {
        As2[0][akp[j]][arow[j]]     = make_uint2(aR[j].x, aR[j].y);
        As2[0][akp[j] + 1][arow[j]] = make_uint2(aR[j].z, aR[j].w);
    }
    #pragma unroll
    for (int j = 0; j < 3; j++)
        *(uint4*)&Bs2[0][bkp[j]][bn2[j]] = bR[j];
    __syncthreads();

    const int T = K >> 5;
    for (int t = 0; t < T; t++) {
        const int s = t & 1;
        if (t + 1 < T) {
            const int kt = 16 * (t + 1);
            #pragma unroll
            for (int j = 0; j < 4; j++) aR[j] = *(const uint4*)(aPtr[j] + kt);
            #pragma unroll
            for (int j = 0; j < 3; j++) bR[j] = *(const uint4*)(bPtr[j] + (size_t)kt * N);
        }

        #pragma unroll
        for (int ks = 0; ks < 2; ks++) {
            const int kb = ks * 8;
            uint2 af[2][4];
            #pragma unroll
            for (int mt = 0; mt < 2; mt++) {
                const int m = wm + mt * 16 + gid;
                af[mt][0] = As2[s][kb + tig    ][m];
                af[mt][1] = As2[s][kb + tig    ][m + 8];
                af[mt][2] = As2[s][kb + tig + 4][m];
                af[mt][3] = As2[s][kb + tig + 4][m + 8];
            }
            uint2 bf[6][2];
            #pragma unroll
            for (int nt = 0; nt < 6; nt++) {
                const int n = wn + nt * 8 + gid;
                bf[nt][0] = Bs2[s][kb + tig    ][n];
                bf[nt][1] = Bs2[s][kb + tig + 4][n];
            }
            #pragma unroll
            for (int mt = 0; mt < 2; mt++)
                #pragma unroll
                for (int nt = 0; nt < 6; nt++) {
                    float* c = acc[mt][nt];
                    mma16(c, af[mt][0].x, af[mt][1].x, af[mt][2].x, af[mt][3].x,
                             bf[nt][0].x, bf[nt][1].x);
                    mma16(c, af[mt][0].x, af[mt][1].x, af[mt][2].x, af[mt][3].x,
                             bf[nt][0].y, bf[nt][1].y);
                    mma16(c, af[mt][0].y, af[mt][1].y, af[mt][2].y, af[mt][3].y,
                             bf[nt][0].x, bf[nt][1].x);
                }
        }

        if (t + 1 < T) {
            const int sn = (t + 1) & 1;
            #pragma unroll
            for (int j = 0; j < 4; j++) {
                As2[sn][akp[j]][arow[j]]     = make_uint2(aR[j].x, aR[j].y);
                As2[sn][akp[j] + 1][arow[j]] = make_uint2(aR[j].z, aR[j].w);
            }
            #pragma unroll
            for (int j = 0; j < 3; j++)
                *(uint4*)&Bs2[sn][bkp[j]][bn2[j]] = bR[j];
        }
        __syncthreads();
    }

    float bb[6][2];
    #pragma unroll
    for (int nt = 0; nt < 6; nt++) {
        int c = n0 + wn + nt * 8 + tig * 2;
        bb[nt][0] = bias[c];
        bb[nt][1] = bias[c + 1];
    }

    #pragma unroll
    for (int mt = 0; mt < 2; mt++) {
        #pragma unroll
        for (int half = 0; half < 2; half++) {
            int r = m0 + wm + mt * 16 + gid + half * 8;
            size_t orow;
            if (MODE == 1) orow = (size_t)map_token(r / NNC, r % NNC);
            else           orow = (size_t)r;
            #pragma unroll
            for (int nt = 0; nt < 6; nt++) {
                float v0 = acc[mt][nt][half * 2 + 0] + bb[nt][0];
                float v1 = acc[mt][nt][half * 2 + 1] + bb[nt][1];
                if (MODE == 2) {
                    v0 = 0.5f * v0 * (1.0f + erff(v0 * 0.70710678118654752f));
                    v1 = 0.5f * v1 * (1.0f + erff(v1 * 0.70710678118654752f));
                    uint2* op2 = outp + orow * (size_t)(N >> 1) + ((n0 + wn) >> 1) + tig;
                    op2[nt * 4] = split_bf16_pair(v0, v1);
                } else {
                    float* op = out + orow * N + n0 + wn + tig * 2 + nt * 8;
                    if (MODE == 1 || MODE == 3) {
                        const float* rp = res + orow * N + n0 + wn + tig * 2 + nt * 8;
                        v0 += rp[0];
                        v1 += rp[1];
                    }
                    *(float2*)op = make_float2(v0, v1);
                }
            }
        }
    }
}

// ---------------- windowed attention: 3-phase, spill-free ----------------
// One block per (window, head), 64 threads. Scores/probs live in smem
// (probs[m][t], owner-thread access only -> no barriers between phases),
// so peak register demand is max(q-phase ~60, pv-phase ~55) regs.
__global__ __launch_bounds__(64, 8)
void attn_kernel(const float* __restrict__ qkv, const float* __restrict__ rpb) {
    __shared__ float ks[NNC * HEADC];        // 6912 B
    __shared__ float vs[NNC * HEADC];        // 6912 B
    __shared__ float probs[NNC * NNC];       // [m][t]  11664 B
    __shared__ float bt[169];
    __shared__ unsigned char fidx_s[49];
    __shared__ int regn_s[NNC];

    const int bw   = blockIdx.x;
    const int head = blockIdx.y;
    const int base = bw * NNC;
    const int tid  = threadIdx.x;

    for (int idx = tid; idx < NNC * HEADC; idx += 64) {
        int m = idx >> 5, d = idx & 31;
        const float* p = qkv + (size_t)(base + m) * (3 * DIMC) + head * HEADC + d;
        ks[idx] = p[DIMC];
        vs[idx] = p[2 * DIMC];
    }
    for (int i = tid; i < 169; i += 64) bt[i] = rpb[i * NHC + head];
    if (tid < 49) fidx_s[tid] = (unsigned char)((tid / 7) * 13 + (tid % 7));
    if (tid < NNC) {
        int i = tid;
        if (i < PC) regn_s[i] = -1;
        else {
            int p = i - PC;
            int r = p / 7, c = p % 7;
            int w = bw & 63;
            int gh = (w >> 3) * 7 + r;
            int gw = (w & 7) * 7 + c;
            int rh = gh < 49 ? 0 : (gh < 53 ? 1 : 2);
            int rw = gw < 49 ? 0 : (gw < 53 ? 1 : 2);
            regn_s[i] = rh * 3 + rw;
        }
    }
    __syncthreads();

    const int t = tid;
    if (t >= NNC) return;

    // Q row (scaled) in registers
    const float4* qp = (const float4*)(qkv + (size_t)(base + t) * (3 * DIMC) + head * HEADC);
    float4 q4[8];
    #pragma unroll
    for (int j = 0; j < 8; j++) {
        q4[j] = qp[j];
        q4[j].x *= SCALEC; q4[j].y *= SCALEC; q4[j].z *= SCALEC; q4[j].w *= SCALEC;
    }

    const bool feat = (t >= PC);
    int tb = 0;
    unsigned mlo = 0, mhi = 0;
    if (feat) {
        int p = t - PC;
        tb = (p / 7 + 6) * 13 + (p % 7 + 6);
        int myreg = regn_s[t];
        #pragma unroll 7
        for (int m = PC; m < NNC; m++) {
            if (regn_s[m] != myreg) {
                if (m < 32) mlo |= 1u << m;
                else        mhi |= 1u << (m - 32);
            }
        }
    }

    // ---- phase A: raw scores -> smem, running max in reg ----
    float mx = -1e30f;
    #pragma unroll 6
    for (int m = 0; m < NNC; m++) {
        const float4* k4 = (const float4*)(ks + m * HEADC);
        float4 k0 = k4[0], k1 = k4[1], k2 = k4[2], k3 = k4[3];
        float4 k5 = k4[4], k6 = k4[5], k7 = k4[6], k8 = k4[7];
        float a0 = q4[0].x * k0.x + q4[0].y * k0.y + q4[0].z * k0.z + q4[0].w * k0.w;
        float a1 = q4[1].x * k1.x + q4[1].y * k1.y + q4[1].z * k1.z + q4[1].w * k1.w;
        float a2 = q4[2].x * k2.x + q4[2].y * k2.y + q4[2].z * k2.z + q4[2].w * k2.w;
        float a3 = q4[3].x * k3.x + q4[3].y * k3.y + q4[3].z * k3.z + q4[3].w * k3.w;
        a0 += q4[4].x * k5.x + q4[4].y * k5.y + q4[4].z * k5.z + q4[4].w * k5.w;
        a1 += q4[5].x * k6.x + q4[5].y * k6.y + q4[5].z * k6.z + q4[5].w * k6.w;
        a2 += q4[6].x * k7.x + q4[6].y * k7.y + q4[6].z * k7.z + q4[6].w * k7.w;
        a3 += q4[7].x * k8.x + q4[7].y * k8.y + q4[7].z * k8.z + q4[7].w * k8.w;
        float a = (a0 + a1) + (a2 + a3);
        if (feat && m >= PC) {
            int idx = tb - (int)fidx_s[m - PC];
            float badd = bt[idx];
            bool msk = (m < 32) ? ((mlo >> m) & 1u) : ((mhi >> (m - 32)) & 1u);
            a += msk ? (badd - 100.f) : badd;
        }
        mx = fmaxf(mx, a);
        probs[m * NNC + t] = a;
    }

    // ---- phase B: exp + sum, write probs back ----
    float sum = 0.f;
    #pragma unroll 6
    for (int m = 0; m < NNC; m++) {
        float e = __expf(probs[m * NNC + t] - mx);
        sum += e;
        probs[m * NNC + t] = e;
    }
    const float inv = 1.0f / sum;

    // ---- phase C: P @ V ----
    float acc[HEADC];
    #pragma unroll
    for (int d = 0; d < HEADC; d++) acc[d] = 0.f;
    #pragma unroll 6
    for (int m = 0; m < NNC; m++) {
        const float pm = probs[m * NNC + t] * inv;
        const float4* v4 = (const float4*)(vs + m * HEADC);
        #pragma unroll
        for (int j = 0; j < 8; j++) {
            float4 vv = v4[j];
            acc[4 * j + 0] += pm * vv.x;
            acc[4 * j + 1] += pm * vv.y;
            acc[4 * j + 2] += pm * vv.z;
            acc[4 * j + 3] += pm * vv.w;
        }
    }

    uint2* op = g_attno_sp + (size_t)(base + t) * 48 + head * 16;
    #pragma unroll
    for (int j = 0; j < 16; j++)
        op[j] = split_bf16_pair(acc[2 * j], acc[2 * j + 1]);
}

// ---------------- launch ----------------
extern "C" void kernel_launch(void* const* d_in, const int* in_sizes, int n_in,
                              void* d_out, int out_size) {
    const float* x       = (const float*)d_in[0];
    const float* norm1_g = (const float*)d_in[1];
    const float* norm1_b = (const float*)d_in[2];
    const float* qkv_w   = (const float*)d_in[3];
    const float* qkv_b   = (const float*)d_in[4];
    const float* rpb     = (const float*)d_in[5];
    const float* proj_w  = (const float*)d_in[6];
    const float* proj_b  = (const float*)d_in[7];
    const float* norm2_g = (const float*)d_in[8];
    const float* norm2_b = (const float*)d_in[9];
    const float* fc1_w   = (const float*)d_in[10];
    const float* fc1_b   = (const float*)d_in[11];
    const float* fc2_w   = (const float*)d_in[12];
    const float* fc2_b   = (const float*)d_in[13];
    float* out = (float*)d_out;

    uint2 *p_xw, *p_attno, *p_yn, *p_h, *p_wq, *p_wp, *p_w1, *p_w2;
    float *p_qkv, *p_y;
    cudaGetSymbolAddress((void**)&p_xw,    g_xw_sp);
    cudaGetSymbolAddress((void**)&p_qkv,   g_qkv);
    cudaGetSymbolAddress((void**)&p_attno, g_attno_sp);
    cudaGetSymbolAddress((void**)&p_y,     g_y);
    cudaGetSymbolAddress((void**)&p_yn,    g_yn_sp);
    cudaGetSymbolAddress((void**)&p_h,     g_h_sp);
    cudaGetSymbolAddress((void**)&p_wq,    g_wq_sp);
    cudaGetSymbolAddress((void**)&p_wp,    g_wp_sp);
    cudaGetSymbolAddress((void**)&p_w1,    g_w1_sp);
    cudaGetSymbolAddress((void**)&p_w2,    g_w2_sp);

    cudaFuncSetAttribute(gemm_tc<0>, cudaFuncAttributeMaxDynamicSharedMemorySize, GEMM_SMEM);
    cudaFuncSetAttribute(gemm_tc<1>, cudaFuncAttributeMaxDynamicSharedMemorySize, GEMM_SMEM);
    cudaFuncSetAttribute(gemm_tc<2>, cudaFuncAttributeMaxDynamicSharedMemorySize, GEMM_SMEM);
    cudaFuncSetAttribute(gemm_tc<3>, cudaFuncAttributeMaxDynamicSharedMemorySize, GEMM_SMEM);

    const int lnBlocks = (MROWS * 32 + 255) / 256;
    const int MB = MROWS / 128;   // 1728

    // 0. pre-split weights
    split_w_kernel<<<216, 256>>>(qkv_w, proj_w, fc1_w, fc2_w);
    // 1. LN1 + window gather (split out)
    ln_gather_kernel<<<lnBlocks, 256>>>(x, norm1_g, norm1_b);
    // 2. QKV GEMM  (N=288, K=96) -> float
    gemm_tc<0><<<dim3(3, MB), 256, GEMM_SMEM>>>(p_xw, p_wq, qkv_b, nullptr, p_qkv, nullptr, 288, 96);
    // 3. windowed attention (split out), one block per (window, head)
    attn_kernel<<<dim3(BATCHC * NWC, NHC), 64>>>(p_qkv, rpb);
    // 4. proj GEMM + scatter + residual-1  (N=96, K=96) -> float y
    gemm_tc<1><<<dim3(1, MB), 256, GEMM_SMEM>>>(p_attno, p_wp, proj_b, x, p_y, nullptr, 96, 96);
    // 5. LN2 (split out)
    ln_plain_kernel<<<lnBlocks, 256>>>(p_y, norm2_g, norm2_b);
    // 6. fc1 + GELU  (N=384, K=96) -> split h
    gemm_tc<2><<<dim3(4, MB), 256, GEMM_SMEM>>>(p_yn, p_w1, fc1_b, nullptr, nullptr, p_h, 384, 96);
    // 7. fc2 + residual-2 -> d_out  (N=96, K=384)
    gemm_tc<3><<<dim3(1, MB), 256, GEMM_SMEM>>>(p_h, p_w2, fc2_b, p_y, out, nullptr, 96, 384);
}